// round 9
// baseline (speedup 1.0000x reference)
#include <cuda_runtime.h>
#include <math.h>
#include <stdint.h>

// ---------------------------------------------------------------------------
// Round 9: weights live in __constant__ memory (LDC/LDCU port) instead of
// shared memory, taking all weight traffic OFF the L1tex pipe. MLP keeps the
// round-4 structure (2 pts/thread, packed fma.rn.f32x2, sync-free); layer 3
// is k-accumulated in two 32-neuron halves so no transpose is needed.
// Phase 1 gather unchanged.
// ---------------------------------------------------------------------------

namespace {

constexpr int L_LEVELS = 16;
constexpr int T_SIZE   = 16384;
constexpr int B_MAX    = 1 << 21;
constexpr int P1_THREADS = 1024;
constexpr int P1_PTS_PER_BLOCK = 16384;
constexpr int P2_THREADS = 128;
constexpr int P2_PTS_PER_THREAD = 2;

typedef unsigned long long u64;

struct NsParams { int ns[L_LEVELS]; };

__device__ float2 g_feats[(size_t)L_LEVELS * B_MAX];   // 256 MB scratch

// ---- constant weight buffer (float offsets, all 16B-aligned) ----
constexpr int C_DW0 = 0;      // [32][64]   2048
constexpr int C_DW1 = 2048;   // [64][16]   1024
constexpr int C_CW0 = 3072;   // [19][64]   1216
constexpr int C_CW1 = 4288;   // [64][64]   4096
constexpr int C_CW2 = 8384;   // [64][3]     192
constexpr int C_DB0 = 8576;   // 64
constexpr int C_DB1 = 8640;   // 16
constexpr int C_CB0 = 8656;   // 64
constexpr int C_CB1 = 8720;   // 64
constexpr int C_CB2 = 8784;   // 3
__constant__ float c_w[8800];

__device__ __forceinline__ void fma2(u64& d, u64 a, u64 b) {
    asm("fma.rn.f32x2 %0, %1, %2, %0;" : "+l"(d) : "l"(a), "l"(b));
}
__device__ __forceinline__ u64 pack2(float lo, float hi) {
    u64 r; asm("mov.b64 %0, {%1, %2};" : "=l"(r) : "f"(lo), "f"(hi)); return r;
}
__device__ __forceinline__ float2 unpack2(u64 v) {
    float2 r; asm("mov.b64 {%0, %1}, %2;" : "=f"(r.x), "=f"(r.y) : "l"(v)); return r;
}
__device__ __forceinline__ float sigmoidf_fast(float v) {
    return 1.0f / (1.0f + __expf(-v));
}
// 128-bit constant load (two packed f32x2 operands)
__device__ __forceinline__ ulonglong2 ldc128(const float* p) {
    return *reinterpret_cast<const ulonglong2*>(p);
}
__device__ __forceinline__ u64 ldc64(const float* p) {
    return *reinterpret_cast<const u64*>(p);
}

// ============================ Phase 1: gather ==============================
__global__ __launch_bounds__(P1_THREADS, 1)
void gather_kernel(const float* __restrict__ x,
                   const float* __restrict__ embed,
                   int B, NsParams nsp)
{
    extern __shared__ float2 stab[];   // T_SIZE float2 = 128 KB

    const int l = blockIdx.y;
    const int n = nsp.ns[l];
    const float nf = (float)n;
    const int np1 = n + 1;
    const bool dense = (np1 * np1 * np1 <= T_SIZE);

    {
        const float4* src = reinterpret_cast<const float4*>(embed) + (size_t)l * (T_SIZE / 2);
        float4* dst = reinterpret_cast<float4*>(stab);
        for (int i = threadIdx.x; i < T_SIZE / 2; i += P1_THREADS) dst[i] = src[i];
    }
    __syncthreads();

    const int base = blockIdx.x * P1_PTS_PER_BLOCK;
    const int end  = min(base + P1_PTS_PER_BLOCK, B);
    float2* featl = g_feats + (size_t)l * B;

    for (int p = base + threadIdx.x; p < end; p += P1_THREADS) {
        const float2* xv = reinterpret_cast<const float2*>(x) + (size_t)p * 3;
        const float2 a0 = __ldg(&xv[0]);
        const float2 a1 = __ldg(&xv[1]);

        float px = fminf(fmaxf((a0.x + 5.0f) * 0.1f, 0.0f), 0.999999f);
        float py = fminf(fmaxf((a0.y + 5.0f) * 0.1f, 0.0f), 0.999999f);
        float pz = fminf(fmaxf((a1.x + 5.0f) * 0.1f, 0.0f), 0.999999f);

        const float xl0 = px * nf, xl1 = py * nf, xl2 = pz * nf;
        const float f0 = floorf(xl0), f1 = floorf(xl1), f2 = floorf(xl2);
        const float w0 = xl0 - f0, w1 = xl1 - f1, w2 = xl2 - f2;
        const float u0 = 1.0f - w0, u1 = 1.0f - w1, u2 = 1.0f - w2;
        const int v0 = (int)f0, v1 = (int)f1, v2 = (int)f2;

        const float q00 = u1 * u2, q01 = u1 * w2, q10 = w1 * u2, q11 = w1 * w2;
        float wgt[8];
        wgt[0] = u0 * q00; wgt[1] = u0 * q01; wgt[2] = u0 * q10; wgt[3] = u0 * q11;
        wgt[4] = w0 * q00; wgt[5] = w0 * q01; wgt[6] = w0 * q10; wgt[7] = w0 * q11;

        int idx[8];
        if (dense) {
            const int bidx = (v0 * np1 + v1) * np1 + v2;
            const int sx = np1 * np1;
            idx[0] = bidx;            idx[1] = bidx + 1;
            idx[2] = bidx + np1;      idx[3] = bidx + np1 + 1;
            idx[4] = bidx + sx;       idx[5] = bidx + sx + 1;
            idx[6] = bidx + sx + np1; idx[7] = bidx + sx + np1 + 1;
        } else {
            const unsigned t1  = (unsigned)v1 * 2654435761u;
            const unsigned t1b = t1 + 2654435761u;
            const unsigned t2  = (unsigned)v2 * 805459861u;
            const unsigned t2b = t2 + 805459861u;
            const unsigned x0  = (unsigned)v0;
            const unsigned x0b = x0 + 1u;
            const unsigned m   = (unsigned)(T_SIZE - 1);
            idx[0] = (int)((x0  ^ t1  ^ t2 ) & m);
            idx[1] = (int)((x0  ^ t1  ^ t2b) & m);
            idx[2] = (int)((x0  ^ t1b ^ t2 ) & m);
            idx[3] = (int)((x0  ^ t1b ^ t2b) & m);
            idx[4] = (int)((x0b ^ t1  ^ t2 ) & m);
            idx[5] = (int)((x0b ^ t1  ^ t2b) & m);
            idx[6] = (int)((x0b ^ t1b ^ t2 ) & m);
            idx[7] = (int)((x0b ^ t1b ^ t2b) & m);
        }

        float acc0 = 0.0f, acc1 = 0.0f;
#pragma unroll
        for (int c = 0; c < 8; c++) {
            const float2 ft = stab[idx[c]];
            acc0 = fmaf(wgt[c], ft.x, acc0);
            acc1 = fmaf(wgt[c], ft.y, acc1);
        }

        featl[p] = make_float2(acc0, acc1);
    }
}

// ============================ Phase 2: MLP =================================
__global__ __launch_bounds__(P2_THREADS)
void mlp_kernel(const float* __restrict__ x,
                float* __restrict__ out, int B)
{
    const int tid = threadIdx.x;

    const int pbase = blockIdx.x * (P2_THREADS * P2_PTS_PER_THREAD) + tid;
    int pt[2];
    pt[0] = pbase;
    pt[1] = pbase + P2_THREADS;
    const bool ok1 = pt[1] < B;
    if (pt[0] >= B) return;
    if (!ok1) pt[1] = pt[0];

    // ---- stage 0: h = db0 + sum_l feat_l @ dW0, packed, 2-pt ILP ----
    u64 hp0[32], hp1[32];
#pragma unroll
    for (int j = 0; j < 16; j++) {
        const ulonglong2 b = ldc128(&c_w[C_DB0 + j * 4]);
        hp0[2 * j] = b.x; hp0[2 * j + 1] = b.y;
        hp1[2 * j] = b.x; hp1[2 * j + 1] = b.y;
    }

    float2 f0 = __ldg(&g_feats[pt[0]]);
    float2 f1 = __ldg(&g_feats[pt[1]]);
#pragma unroll
    for (int l = 0; l < L_LEVELS; l++) {
        float2 nf0, nf1;
        if (l + 1 < L_LEVELS) {
            nf0 = __ldg(&g_feats[(size_t)(l + 1) * B + pt[0]]);
            nf1 = __ldg(&g_feats[(size_t)(l + 1) * B + pt[1]]);
        }
        const u64 a00 = pack2(f0.x, f0.x), a01 = pack2(f0.y, f0.y);
        const u64 a10 = pack2(f1.x, f1.x), a11 = pack2(f1.y, f1.y);
        const float* r0 = &c_w[C_DW0 + (2 * l) * 64];
        const float* r1 = &c_w[C_DW0 + (2 * l + 1) * 64];
#pragma unroll
        for (int j = 0; j < 16; j++) {
            const ulonglong2 w0 = ldc128(r0 + j * 4);
            const ulonglong2 w1 = ldc128(r1 + j * 4);
            fma2(hp0[2 * j],     a00, w0.x);
            fma2(hp0[2 * j + 1], a00, w0.y);
            fma2(hp1[2 * j],     a10, w0.x);
            fma2(hp1[2 * j + 1], a10, w0.y);
            fma2(hp0[2 * j],     a01, w1.x);
            fma2(hp0[2 * j + 1], a01, w1.y);
            fma2(hp1[2 * j],     a11, w1.x);
            fma2(hp1[2 * j + 1], a11, w1.y);
        }
        f0 = nf0; f1 = nf1;
    }

    // ---- layer 1: h2 = relu(h) @ dW1 + db1  (64 -> 16) ----
    u64 hq0[8], hq1[8];
#pragma unroll
    for (int m = 0; m < 4; m++) {
        const ulonglong2 b = ldc128(&c_w[C_DB1 + m * 4]);
        hq0[2 * m] = b.x; hq0[2 * m + 1] = b.y;
        hq1[2 * m] = b.x; hq1[2 * m + 1] = b.y;
    }
#pragma unroll
    for (int j2 = 0; j2 < 32; j2++) {
        const float2 v0 = unpack2(hp0[j2]);
        const float2 v1 = unpack2(hp1[j2]);
        const float r00 = fmaxf(v0.x, 0.0f), r01 = fmaxf(v0.y, 0.0f);
        const float r10 = fmaxf(v1.x, 0.0f), r11 = fmaxf(v1.y, 0.0f);
        const u64 p00 = pack2(r00, r00);
        const u64 p01 = pack2(r01, r01);
        const u64 p10 = pack2(r10, r10);
        const u64 p11 = pack2(r11, r11);
        const float* w0 = &c_w[C_DW1 + (2 * j2) * 16];
        const float* w1 = &c_w[C_DW1 + (2 * j2 + 1) * 16];
#pragma unroll
        for (int m = 0; m < 4; m++) {
            const ulonglong2 wa = ldc128(w0 + m * 4);
            const ulonglong2 wb = ldc128(w1 + m * 4);
            fma2(hq0[2 * m],     p00, wa.x);
            fma2(hq0[2 * m + 1], p00, wa.y);
            fma2(hq1[2 * m],     p10, wa.x);
            fma2(hq1[2 * m + 1], p10, wa.y);
            fma2(hq0[2 * m],     p01, wb.x);
            fma2(hq0[2 * m + 1], p01, wb.y);
            fma2(hq1[2 * m],     p11, wb.x);
            fma2(hq1[2 * m + 1], p11, wb.y);
        }
    }

    float h2a[16], h2b[16];
#pragma unroll
    for (int m = 0; m < 8; m++) {
        const float2 va = unpack2(hq0[m]);
        const float2 vb = unpack2(hq1[m]);
        h2a[2 * m] = va.x; h2a[2 * m + 1] = va.y;
        h2b[2 * m] = vb.x; h2b[2 * m + 1] = vb.y;
    }

    const float dens0 = sigmoidf_fast(h2a[0]);
    const float dens1 = sigmoidf_fast(h2b[0]);

    // ---- cin = [density, relu(h2[1:16]), view] ----
    float cina[19], cinb[19];
    cina[0] = dens0; cinb[0] = dens1;
#pragma unroll
    for (int m = 1; m < 16; m++) {
        cina[m] = fmaxf(h2a[m], 0.0f);
        cinb[m] = fmaxf(h2b[m], 0.0f);
    }
    {
        const float2* xv0 = reinterpret_cast<const float2*>(x) + (size_t)pt[0] * 3;
        const float2* xv1 = reinterpret_cast<const float2*>(x) + (size_t)pt[1] * 3;
        const float2 b1a = __ldg(&xv0[1]); const float2 b2a = __ldg(&xv0[2]);
        const float2 b1b = __ldg(&xv1[1]); const float2 b2b = __ldg(&xv1[2]);
        cina[16] = b1a.y; cina[17] = b2a.x; cina[18] = b2a.y;
        cinb[16] = b1b.y; cinb[17] = b2b.x; cinb[18] = b2b.y;
    }

    // ---- c1 = relu(cin @ cW0 + cb0)  (19 -> 64) ----
    u64 c1p0[32], c1p1[32];
#pragma unroll
    for (int j = 0; j < 16; j++) {
        const ulonglong2 b = ldc128(&c_w[C_CB0 + j * 4]);
        c1p0[2 * j] = b.x; c1p0[2 * j + 1] = b.y;
        c1p1[2 * j] = b.x; c1p1[2 * j + 1] = b.y;
    }
#pragma unroll
    for (int k = 0; k < 19; k++) {
        const u64 ca = pack2(cina[k], cina[k]);
        const u64 cb = pack2(cinb[k], cinb[k]);
        const float* wr = &c_w[C_CW0 + k * 64];
#pragma unroll
        for (int j = 0; j < 16; j++) {
            const ulonglong2 w = ldc128(wr + j * 4);
            fma2(c1p0[2 * j],     ca, w.x);
            fma2(c1p0[2 * j + 1], ca, w.y);
            fma2(c1p1[2 * j],     cb, w.x);
            fma2(c1p1[2 * j + 1], cb, w.y);
        }
    }
#pragma unroll
    for (int j = 0; j < 32; j++) {
        float2 va = unpack2(c1p0[j]);
        float2 vb = unpack2(c1p1[j]);
        c1p0[j] = pack2(fmaxf(va.x, 0.0f), fmaxf(va.y, 0.0f));
        c1p1[j] = pack2(fmaxf(vb.x, 0.0f), fmaxf(vb.y, 0.0f));
    }

    // ---- c2 = relu(c1 @ cW1 + cb1) in two 32-neuron halves (k-accumulated,
    //      row-major cW1, no transpose), streamed into cW2 -> color ----
    float col[2][3];
    col[0][0] = c_w[C_CB2 + 0]; col[0][1] = c_w[C_CB2 + 1]; col[0][2] = c_w[C_CB2 + 2];
    col[1][0] = col[0][0];      col[1][1] = col[0][1];      col[1][2] = col[0][2];

#pragma unroll
    for (int half = 0; half < 2; half++) {
        u64 acc0[16], acc1[16];
#pragma unroll
        for (int j = 0; j < 8; j++) {
            const ulonglong2 b = ldc128(&c_w[C_CB1 + half * 32 + j * 4]);
            acc0[2 * j] = b.x; acc0[2 * j + 1] = b.y;
            acc1[2 * j] = b.x; acc1[2 * j + 1] = b.y;
        }
#pragma unroll
        for (int kp = 0; kp < 32; kp++) {
            const float2 u0 = unpack2(c1p0[kp]);
            const float2 u1 = unpack2(c1p1[kp]);
            const u64 a00 = pack2(u0.x, u0.x), a01 = pack2(u0.y, u0.y);
            const u64 a10 = pack2(u1.x, u1.x), a11 = pack2(u1.y, u1.y);
            const float* r0 = &c_w[C_CW1 + (2 * kp) * 64 + half * 32];
            const float* r1 = &c_w[C_CW1 + (2 * kp + 1) * 64 + half * 32];
#pragma unroll
            for (int j = 0; j < 8; j++) {
                const ulonglong2 w0 = ldc128(r0 + j * 4);
                const ulonglong2 w1 = ldc128(r1 + j * 4);
                fma2(acc0[2 * j],     a00, w0.x);
                fma2(acc0[2 * j + 1], a00, w0.y);
                fma2(acc1[2 * j],     a10, w0.x);
                fma2(acc1[2 * j + 1], a10, w0.y);
                fma2(acc0[2 * j],     a01, w1.x);
                fma2(acc0[2 * j + 1], a01, w1.y);
                fma2(acc1[2 * j],     a11, w1.x);
                fma2(acc1[2 * j + 1], a11, w1.y);
            }
        }
        // relu + stream into cW2 columns
#pragma unroll
        for (int jp = 0; jp < 16; jp++) {
            const int n0 = half * 32 + 2 * jp;
            const float2 va = unpack2(acc0[jp]);
            const float2 vb = unpack2(acc1[jp]);
            const float a0 = fmaxf(va.x, 0.0f), a1 = fmaxf(va.y, 0.0f);
            const float b0 = fmaxf(vb.x, 0.0f), b1 = fmaxf(vb.y, 0.0f);
            const float w00 = c_w[C_CW2 + n0 * 3 + 0];
            const float w01 = c_w[C_CW2 + n0 * 3 + 1];
            const float w02 = c_w[C_CW2 + n0 * 3 + 2];
            const float w10 = c_w[C_CW2 + n0 * 3 + 3];
            const float w11 = c_w[C_CW2 + n0 * 3 + 4];
            const float w12 = c_w[C_CW2 + n0 * 3 + 5];
            col[0][0] = fmaf(a0, w00, col[0][0]);
            col[0][1] = fmaf(a0, w01, col[0][1]);
            col[0][2] = fmaf(a0, w02, col[0][2]);
            col[0][0] = fmaf(a1, w10, col[0][0]);
            col[0][1] = fmaf(a1, w11, col[0][1]);
            col[0][2] = fmaf(a1, w12, col[0][2]);
            col[1][0] = fmaf(b0, w00, col[1][0]);
            col[1][1] = fmaf(b0, w01, col[1][1]);
            col[1][2] = fmaf(b0, w02, col[1][2]);
            col[1][0] = fmaf(b1, w10, col[1][0]);
            col[1][1] = fmaf(b1, w11, col[1][1]);
            col[1][2] = fmaf(b1, w12, col[1][2]);
        }
    }

    reinterpret_cast<float4*>(out)[pt[0]] =
        make_float4(dens0, sigmoidf_fast(col[0][0]), sigmoidf_fast(col[0][1]), sigmoidf_fast(col[0][2]));
    if (ok1) {
        reinterpret_cast<float4*>(out)[pt[1]] =
            make_float4(dens1, sigmoidf_fast(col[1][0]), sigmoidf_fast(col[1][1]), sigmoidf_fast(col[1][2]));
    }
}

} // anonymous namespace

extern "C" void kernel_launch(void* const* d_in, const int* in_sizes, int n_in,
                              void* d_out, int out_size)
{
    const float* x    = (const float*)d_in[0];
    const float* emb  = (const float*)d_in[1];
    float* out = (float*)d_out;

    const int B = in_sizes[0] / 6;

    NsParams nsp;
    const double g = exp((log(512.0) - log(16.0)) / 15.0);
    for (int i = 0; i < L_LEVELS; i++) {
        nsp.ns[i] = (int)(16.0 * pow(g, (double)i));
    }

    static bool attr_set = false;
    if (!attr_set) {
        cudaFuncSetAttribute(gather_kernel,
                             cudaFuncAttributeMaxDynamicSharedMemorySize,
                             T_SIZE * (int)sizeof(float2));
        attr_set = true;
    }

    // populate constant weight bank (D2D memcpys; graph-capturable)
    cudaMemcpyToSymbolAsync(c_w, d_in[2],  2048 * 4, C_DW0 * 4, cudaMemcpyDeviceToDevice, 0);
    cudaMemcpyToSymbolAsync(c_w, d_in[3],    64 * 4, C_DB0 * 4, cudaMemcpyDeviceToDevice, 0);
    cudaMemcpyToSymbolAsync(c_w, d_in[4],  1024 * 4, C_DW1 * 4, cudaMemcpyDeviceToDevice, 0);
    cudaMemcpyToSymbolAsync(c_w, d_in[5],    16 * 4, C_DB1 * 4, cudaMemcpyDeviceToDevice, 0);
    cudaMemcpyToSymbolAsync(c_w, d_in[6],  1216 * 4, C_CW0 * 4, cudaMemcpyDeviceToDevice, 0);
    cudaMemcpyToSymbolAsync(c_w, d_in[7],    64 * 4, C_CB0 * 4, cudaMemcpyDeviceToDevice, 0);
    cudaMemcpyToSymbolAsync(c_w, d_in[8],  4096 * 4, C_CW1 * 4, cudaMemcpyDeviceToDevice, 0);
    cudaMemcpyToSymbolAsync(c_w, d_in[9],    64 * 4, C_CB1 * 4, cudaMemcpyDeviceToDevice, 0);
    cudaMemcpyToSymbolAsync(c_w, d_in[10],  192 * 4, C_CW2 * 4, cudaMemcpyDeviceToDevice, 0);
    cudaMemcpyToSymbolAsync(c_w, d_in[11],    3 * 4, C_CB2 * 4, cudaMemcpyDeviceToDevice, 0);

    const int nb1 = (B + P1_PTS_PER_BLOCK - 1) / P1_PTS_PER_BLOCK;
    dim3 grid1(nb1, L_LEVELS);
    gather_kernel<<<grid1, P1_THREADS, T_SIZE * sizeof(float2)>>>(x, emb, B, nsp);

    const int ptsPerBlock2 = P2_THREADS * P2_PTS_PER_THREAD;
    const int nb2 = (B + ptsPerBlock2 - 1) / ptsPerBlock2;
    mlp_kernel<<<nb2, P2_THREADS>>>(x, out, B);
}